// round 11
// baseline (speedup 1.0000x reference)
#include <cuda_runtime.h>
#include <cuda_bf16.h>
#include <cstdint>

// RVQ: x [16,2048,128] f32, codebooks [8,1024,128] f32
// out (float32): indices [B*N*Q] ++ quantized [B*N*D] ++ commits [Q]
// Core: single-product bf16 HMMA filter + per-lane top-3 + exact fp32 rescue.

#define TOKENS   32768
#define DDIM     128
#define KCODES   1024
#define QSTAGES  8
#define BM       128
#define NTILE    64
#define NTILES   (KCODES / NTILE)   // 16
#define NTHREADS 512
#define NBLOCKS  (TOKENS / BM)      // 256

#define A_BYTES      32768   // 128 rows x 256 B (bf16 plane)
#define B_TILE_BYTES 16384   // 64 rows x 256 B
#define A_OFF        0
#define B_OFF        32768   // 3 buffers x 16384
#define CAND_OFF     81920   // [2][128][4][3] int = 12288
#define RESV_OFF     94208   // [4][128] f32
#define RESI_OFF     96256   // [4][128] int
#define CHOSEN_OFF   98304   // [128] int
#define SMEM_TOTAL   98816

__device__ float g_res[TOKENS * DDIM];
__device__ float g_c2[QSTAGES * KCODES];
__device__ float g_partial[QSTAGES * NBLOCKS];
__device__ unsigned char g_cbs[(size_t)QSTAGES * NTILES * B_TILE_BYTES]; // 2MB

// ---------------------------------------------------------------------------
__device__ __forceinline__ void cp16(uint32_t dst, const void* src) {
    asm volatile("cp.async.cg.shared.global [%0], [%1], 16;" :: "r"(dst), "l"(src));
}
__device__ __forceinline__ void cp_commit() { asm volatile("cp.async.commit_group;"); }
template<int N> __device__ __forceinline__ void cp_wait() {
    asm volatile("cp.async.wait_group %0;" :: "n"(N) : "memory");
}
__device__ __forceinline__ uint32_t smem_u32(const void* p) {
    uint32_t a;
    asm("{ .reg .u64 t; cvta.to.shared.u64 t, %1; cvt.u32.u64 %0, t; }" : "=r"(a) : "l"(p));
    return a;
}
__device__ __forceinline__ void ldsm4(uint32_t& r0, uint32_t& r1, uint32_t& r2,
                                      uint32_t& r3, uint32_t addr) {
    asm volatile("ldmatrix.sync.aligned.m8n8.x4.shared.b16 {%0,%1,%2,%3}, [%4];"
                 : "=r"(r0), "=r"(r1), "=r"(r2), "=r"(r3) : "r"(addr));
}
__device__ __forceinline__ void mma16816(float& d0, float& d1, float& d2, float& d3,
                                         uint32_t a0, uint32_t a1, uint32_t a2,
                                         uint32_t a3, uint32_t b0, uint32_t b1) {
    asm volatile(
        "mma.sync.aligned.m16n8k16.row.col.f32.bf16.bf16.f32 "
        "{%0,%1,%2,%3}, {%4,%5,%6,%7}, {%8,%9}, {%0,%1,%2,%3};"
        : "+f"(d0), "+f"(d1), "+f"(d2), "+f"(d3)
        : "r"(a0), "r"(a1), "r"(a2), "r"(a3), "r"(b0), "r"(b1));
}
__device__ __forceinline__ bool dless(float a, int ia, float b, int ib) {
    return a < b || (a == b && ia < ib);
}
// insert into ascending top-3 (v1<=v2<=v3); ties keep earlier entries (superset ok)
__device__ __forceinline__ void ins3(float d, int idx,
                                     float& v1, int& i1, float& v2, int& i2,
                                     float& v3, int& i3) {
    if (d < v3) {
        if (d < v2) {
            v3 = v2; i3 = i2;
            if (d < v1) { v2 = v1; i2 = i1; v1 = d; i1 = idx; }
            else        { v2 = d;  i2 = idx; }
        } else { v3 = d; i3 = idx; }
    }
}

// smem element (row, bf16-col c) -> byte:  r*256 + ((c>>3) ^ (r&7))*16 + (c&7)*2
__device__ __forceinline__ uint2 pack_bf16x4(float4 v) {
    unsigned short h0 = __bfloat16_as_ushort(__float2bfloat16_rn(v.x));
    unsigned short h1 = __bfloat16_as_ushort(__float2bfloat16_rn(v.y));
    unsigned short h2 = __bfloat16_as_ushort(__float2bfloat16_rn(v.z));
    unsigned short h3 = __bfloat16_as_ushort(__float2bfloat16_rn(v.w));
    uint2 r;
    r.x = h0 | ((uint32_t)h1 << 16);
    r.y = h2 | ((uint32_t)h3 << 16);
    return r;
}

// ---------------------------------------------------------------------------
// prep: codebooks -> bf16 plane in ldmatrix-swizzled 16KB tile images.
// ---------------------------------------------------------------------------
__global__ void prep_kernel(const float* __restrict__ cb) {
    int gr = blockIdx.x * blockDim.x + threadIdx.x;   // 0..8191
    if (gr >= QSTAGES * KCODES) return;
    int stage = gr >> 10, row = gr & 1023;
    int tile = row >> 6, r = row & 63;
    const float4* src = (const float4*)(cb + (size_t)gr * DDIM);
    unsigned char* base = g_cbs + (size_t)(stage * NTILES + tile) * B_TILE_BYTES;
    #pragma unroll 4
    for (int c4 = 0; c4 < 32; c4++) {
        uint2 H = pack_bf16x4(src[c4]);
        uint32_t so = (uint32_t)r * 256 + (uint32_t)(((c4 >> 1) ^ (r & 7)) * 16)
                    + (uint32_t)((c4 & 1) * 8);
        *(uint2*)(base + so) = H;
    }
}

// ---------------------------------------------------------------------------
__global__ void c2_kernel(const float* __restrict__ cb) {
    int warp = (blockIdx.x * blockDim.x + threadIdx.x) >> 5;
    int lane = threadIdx.x & 31;
    const float4* row = (const float4*)(cb + (size_t)warp * DDIM);
    float4 v = row[lane];
    float s = v.x * v.x + v.y * v.y + v.z * v.z + v.w * v.w;
    #pragma unroll
    for (int o = 16; o > 0; o >>= 1) s += __shfl_down_sync(0xffffffffu, s, o);
    if (lane == 0) g_c2[warp] = s;
}

// ---------------------------------------------------------------------------
extern __shared__ char sm[];

__global__ __launch_bounds__(NTHREADS, 1)
void stage_kernel(const float* __restrict__ x,
                  const float* __restrict__ cb_all,
                  float* __restrict__ out,
                  int stage, int is_last) {
    const uint32_t smb = smem_u32(sm);
    const int tid = threadIdx.x, wid = tid >> 5, lid = tid & 31;
    const int tok0 = blockIdx.x * BM;
    const int warpM = wid & 7, warpN = wid >> 3;   // 8 x 2 warp grid
    const float*  src = (stage == 0) ? x : (const float*)g_res;
    const float*  cbf = cb_all + (size_t)stage * KCODES * DDIM;
    const float4* cb4 = (const float4*)cbf;
    const float*  c2  = g_c2 + stage * KCODES;

    int*   cand   = (int*)(sm + CAND_OFF);
    float* resv   = (float*)(sm + RESV_OFF);
    int*   resi   = (int*)(sm + RESI_OFF);
    int*   chosen = (int*)(sm + CHOSEN_OFF);

    // ---- preload B tiles 0,1 into buffers 0,1 ----
    const unsigned char* gcb = g_cbs + (size_t)(stage * NTILES) * B_TILE_BYTES;
    {
        uint32_t b0 = smb + B_OFF, b1 = smb + B_OFF + B_TILE_BYTES;
        #pragma unroll
        for (int k = 0; k < 2; k++) {
            int u = tid + k * NTHREADS;   // 0..1023
            cp16(b0 + (uint32_t)u * 16, gcb + (size_t)u * 16);
        }
        cp_commit();
        #pragma unroll
        for (int k = 0; k < 2; k++) {
            int u = tid + k * NTHREADS;
            cp16(b1 + (uint32_t)u * 16, gcb + B_TILE_BYTES + (size_t)u * 16);
        }
        cp_commit();
    }

    // ---- A: residual -> bf16 plane in swizzled smem ----
    {
        const float4* s4 = (const float4*)src + (size_t)tok0 * 32;
        #pragma unroll
        for (int k = 0; k < 8; k++) {
            int f = tid + k * NTHREADS;
            int r = f >> 5, c4 = f & 31;
            uint2 H = pack_bf16x4(s4[f]);
            uint32_t so = (uint32_t)r * 256 + (uint32_t)(((c4 >> 1) ^ (r & 7)) * 16)
                        + (uint32_t)((c4 & 1) * 8);
            *(uint2*)(sm + A_OFF + so) = H;
        }
    }
    __syncthreads();

    // lane addressing
    const int arow = warpM * 16 + (lid & 15);
    const uint32_t aRowByte = (uint32_t)arow * 256;
    const uint32_t aRx = (uint32_t)(arow & 7);
    const uint32_t aKh = (uint32_t)(lid >> 4);
    uint32_t bRowByte[2], bRx[2];
    #pragma unroll
    for (int pi = 0; pi < 2; pi++) {
        int row = warpN * 32 + pi * 16 + ((lid >> 4) << 3) + (lid & 7);
        bRowByte[pi] = (uint32_t)row * 256;
        bRx[pi] = (uint32_t)(row & 7);
    }
    const uint32_t bKh = (uint32_t)((lid >> 3) & 1);

    // per-thread per-h top-3 (h rows: warpM*16 + h*8 + lid/4)
    float v1[2], v2[2], v3[2]; int i1[2], i2[2], i3[2];
    #pragma unroll
    for (int h = 0; h < 2; h++) {
        v1[h] = 3.4e38f; v2[h] = 3.4e38f; v3[h] = 3.4e38f;
        i1[h] = 0; i2[h] = 0; i3[h] = 0;
    }

    for (int t = 0; t < NTILES; t++) {
        if (t < NTILES - 1) cp_wait<1>(); else cp_wait<0>();
        __syncthreads();
        // prefetch tile t+2 into buffer (t+2)%3 (last read at t-1, safe after sync)
        if (t + 2 < NTILES) {
            uint32_t bb = smb + B_OFF + (uint32_t)((t + 2) % 3) * B_TILE_BYTES;
            const unsigned char* gs = gcb + (size_t)(t + 2) * B_TILE_BYTES;
            #pragma unroll
            for (int k = 0; k < 2; k++) {
                int u = tid + k * NTHREADS;
                cp16(bb + (uint32_t)u * 16, gs + (size_t)u * 16);
            }
            cp_commit();
        }
        const uint32_t bbuf = smb + B_OFF + (uint32_t)(t % 3) * B_TILE_BYTES;

        float acc[4][4];
        #pragma unroll
        for (int ni = 0; ni < 4; ni++)
            #pragma unroll
            for (int q = 0; q < 4; q++) acc[ni][q] = 0.f;

        #pragma unroll
        for (int k8 = 0; k8 < 8; k8++) {
            const uint32_t ku = (uint32_t)(2 * k8);
            uint32_t a[4];
            {
                uint32_t addr = smb + A_OFF + aRowByte + (((ku + aKh) ^ aRx) << 4);
                ldsm4(a[0], a[1], a[2], a[3], addr);
            }
            uint32_t b[2][4];
            #pragma unroll
            for (int pi = 0; pi < 2; pi++) {
                uint32_t addr = bbuf + bRowByte[pi] + (((ku + bKh) ^ bRx[pi]) << 4);
                ldsm4(b[pi][0], b[pi][1], b[pi][2], b[pi][3], addr);
            }
            #pragma unroll
            for (int pi = 0; pi < 2; pi++) {
                mma16816(acc[pi*2][0], acc[pi*2][1], acc[pi*2][2], acc[pi*2][3],
                         a[0], a[1], a[2], a[3], b[pi][0], b[pi][1]);
                mma16816(acc[pi*2+1][0], acc[pi*2+1][1], acc[pi*2+1][2], acc[pi*2+1][3],
                         a[0], a[1], a[2], a[3], b[pi][2], b[pi][3]);
            }
        }

        // top-3 epilogue
        const int codebase = t * NTILE + warpN * 32;
        #pragma unroll
        for (int ni = 0; ni < 4; ni++) {
            int code0 = codebase + ni * 8 + (lid & 3) * 2;
            float2 cc = __ldg((const float2*)(c2 + code0));
            #pragma unroll
            for (int h = 0; h < 2; h++) {
                float d0 = cc.x - 2.f * acc[ni][h * 2];
                float d1 = cc.y - 2.f * acc[ni][h * 2 + 1];
                ins3(d0, code0,     v1[h], i1[h], v2[h], i2[h], v3[h], i3[h]);
                ins3(d1, code0 + 1, v1[h], i1[h], v2[h], i2[h], v3[h], i3[h]);
            }
        }
        __syncthreads();   // all warps done with buffer t%3 before its refill at t+1
    }

    // write per-lane candidates: cand[warpN][row][lane&3][0..2]
    #pragma unroll
    for (int h = 0; h < 2; h++) {
        int row = warpM * 16 + h * 8 + (lid >> 2);
        int* myc = cand + ((warpN * 128 + row) * 4 + (lid & 3)) * 3;
        myc[0] = i1[h]; myc[1] = i2[h]; myc[2] = i3[h];
    }
    __syncthreads();

    // exact fp32 rescue: thread = (token, slot); slot covers contributor c=slot>>1,
    // lane classes {2*(slot&1), 2*(slot&1)+1}: 6 candidates each.
    {
        const int token = tid >> 2, slot = tid & 3;
        const float* rrow = src + (size_t)(tok0 + token) * DDIM;
        float bv = 3.4e38f; int bi = 0x7fffffff;
        #pragma unroll
        for (int l = 0; l < 2; l++) {
            int lane4 = (slot & 1) * 2 + l;
            const int* cc = cand + (((slot >> 1) * 128 + token) * 4 + lane4) * 3;
            #pragma unroll
            for (int q = 0; q < 3; q++) {
                int j = cc[q];
                const float* crow = cbf + (size_t)j * DDIM;
                float acc1 = 0.f;
                #pragma unroll 16
                for (int d = 0; d < DDIM; d++)
                    acc1 = fmaf(__ldg(&rrow[d]), __ldg(&crow[d]), acc1);
                float dd = __ldg(&c2[j]) - 2.f * acc1;
                if (dless(dd, j, bv, bi)) { bv = dd; bi = j; }
            }
        }
        resv[slot * 128 + token] = bv;
        resi[slot * 128 + token] = bi;
    }
    __syncthreads();
    if (tid < BM) {
        float bv = 3.4e38f; int bi = 0x7fffffff;
        #pragma unroll
        for (int s = 0; s < 4; s++) {
            float v = resv[s * 128 + tid];
            int   j = resi[s * 128 + tid];
            if (dless(v, j, bv, bi)) { bv = v; bi = j; }
        }
        chosen[tid] = bi;
        out[(size_t)(tok0 + tid) * QSTAGES + stage] = (float)bi;
    }
    __syncthreads();

    // residual update + commit partial + optional quantized output (fp32 exact)
    float4*       res4 = (float4*)g_res + (size_t)tok0 * 32;
    const float4* s4   = (const float4*)src + (size_t)tok0 * 32;
    const float4* x4   = (const float4*)x + (size_t)tok0 * 32;
    float4*       q4   = (float4*)(out + (size_t)TOKENS * QSTAGES) + (size_t)tok0 * 32;

    float psum = 0.f;
    #pragma unroll
    for (int k = 0; k < 8; k++) {
        int f = tid + k * NTHREADS;
        int tk = f >> 5, d4 = f & 31;
        float4 rv = s4[f];
        float4 cv = cb4[(size_t)chosen[tk] * 32 + d4];
        float4 nv = make_float4(rv.x - cv.x, rv.y - cv.y, rv.z - cv.z, rv.w - cv.w);
        res4[tk * 32 + d4] = nv;
        psum += nv.x * nv.x + nv.y * nv.y + nv.z * nv.z + nv.w * nv.w;
        if (is_last) {
            float4 xv = x4[f];
            q4[tk * 32 + d4] = make_float4(xv.x - nv.x, xv.y - nv.y,
                                           xv.z - nv.z, xv.w - nv.w);
        }
    }
    #pragma unroll
    for (int o = 16; o > 0; o >>= 1) psum += __shfl_down_sync(0xffffffffu, psum, o);
    __syncthreads();
    if (lid == 0) resv[wid] = psum;
    __syncthreads();
    if (tid == 0) {
        float s = 0.f;
        #pragma unroll
        for (int w2 = 0; w2 < 16; w2++) s += resv[w2];
        g_partial[stage * NBLOCKS + blockIdx.x] = s;
    }
}

// ---------------------------------------------------------------------------
__global__ void finish_kernel(float* __restrict__ out) {
    int q = threadIdx.x;
    if (q < QSTAGES) {
        float s = 0.f;
        for (int b = 0; b < NBLOCKS; b++) s += g_partial[q * NBLOCKS + b];
        out[(size_t)TOKENS * QSTAGES + (size_t)TOKENS * DDIM + q] =
            s / (float)(TOKENS * DDIM);
    }
}

extern "C" void kernel_launch(void* const* d_in, const int* in_sizes, int n_in,
                              void* d_out, int out_size) {
    const float* x  = (const float*)d_in[0];
    const float* cb = (const float*)d_in[1];
    float* out = (float*)d_out;

    cudaFuncSetAttribute(stage_kernel,
                         cudaFuncAttributeMaxDynamicSharedMemorySize, SMEM_TOTAL);

    prep_kernel<<<64, 128>>>(cb);
    c2_kernel<<<1024, 256>>>(cb);
    for (int s = 0; s < QSTAGES; s++) {
        stage_kernel<<<NBLOCKS, NTHREADS, SMEM_TOTAL>>>(x, cb, out, s,
                                                        (s == QSTAGES - 1) ? 1 : 0);
    }
    finish_kernel<<<1, 32>>>(out);
}

// round 12
// speedup vs baseline: 4.3579x; 4.3579x over previous
#include <cuda_runtime.h>
#include <cuda_bf16.h>
#include <cstdint>

// RVQ: x [16,2048,128] f32, codebooks [8,1024,128] f32
// out (float32): indices [B*N*Q] ++ quantized [B*N*D] ++ commits [Q]
// Core: single-product bf16 HMMA filter + per-lane top-3 + warp-coalesced
// exact fp32 rescue (24 candidates/token).

#define TOKENS   32768
#define DDIM     128
#define KCODES   1024
#define QSTAGES  8
#define BM       128
#define NTILE    64
#define NTILES   (KCODES / NTILE)   // 16
#define NTHREADS 512
#define NBLOCKS  (TOKENS / BM)      // 256

#define A_BYTES      32768   // 128 rows x 256 B (bf16 plane)
#define B_TILE_BYTES 16384
#define A_OFF        0
#define B_OFF        32768   // 3 buffers x 16384 -> ends 81920
#define RES_OFF      0       // fp32 residual overlay (64KB), after mainloop
#define CAND_OFF     81920   // [128][24] int = 12288
#define CHOSEN_OFF   94208   // [128] int
#define PSUM_OFF     94720   // [16] float
#define SMEM_TOTAL   94784

__device__ float g_res[TOKENS * DDIM];
__device__ float g_c2[QSTAGES * KCODES];
__device__ float g_partial[QSTAGES * NBLOCKS];
__device__ unsigned char g_cbs[(size_t)QSTAGES * NTILES * B_TILE_BYTES]; // 2MB

// ---------------------------------------------------------------------------
__device__ __forceinline__ void cp16(uint32_t dst, const void* src) {
    asm volatile("cp.async.cg.shared.global [%0], [%1], 16;" :: "r"(dst), "l"(src));
}
__device__ __forceinline__ void cp_commit() { asm volatile("cp.async.commit_group;"); }
template<int N> __device__ __forceinline__ void cp_wait() {
    asm volatile("cp.async.wait_group %0;" :: "n"(N) : "memory");
}
__device__ __forceinline__ uint32_t smem_u32(const void* p) {
    uint32_t a;
    asm("{ .reg .u64 t; cvta.to.shared.u64 t, %1; cvt.u32.u64 %0, t; }" : "=r"(a) : "l"(p));
    return a;
}
__device__ __forceinline__ void ldsm4(uint32_t& r0, uint32_t& r1, uint32_t& r2,
                                      uint32_t& r3, uint32_t addr) {
    asm volatile("ldmatrix.sync.aligned.m8n8.x4.shared.b16 {%0,%1,%2,%3}, [%4];"
                 : "=r"(r0), "=r"(r1), "=r"(r2), "=r"(r3) : "r"(addr));
}
__device__ __forceinline__ void mma16816(float& d0, float& d1, float& d2, float& d3,
                                         uint32_t a0, uint32_t a1, uint32_t a2,
                                         uint32_t a3, uint32_t b0, uint32_t b1) {
    asm volatile(
        "mma.sync.aligned.m16n8k16.row.col.f32.bf16.bf16.f32 "
        "{%0,%1,%2,%3}, {%4,%5,%6,%7}, {%8,%9}, {%0,%1,%2,%3};"
        : "+f"(d0), "+f"(d1), "+f"(d2), "+f"(d3)
        : "r"(a0), "r"(a1), "r"(a2), "r"(a3), "r"(b0), "r"(b1));
}
__device__ __forceinline__ bool dless(float a, int ia, float b, int ib) {
    return a < b || (a == b && ia < ib);
}
__device__ __forceinline__ void ins3(float d, int idx,
                                     float& v1, int& i1, float& v2, int& i2,
                                     float& v3, int& i3) {
    if (d < v3) {
        if (d < v2) {
            v3 = v2; i3 = i2;
            if (d < v1) { v2 = v1; i2 = i1; v1 = d; i1 = idx; }
            else        { v2 = d;  i2 = idx; }
        } else { v3 = d; i3 = idx; }
    }
}
__device__ __forceinline__ uint2 pack_bf16x4(float4 v) {
    unsigned short h0 = __bfloat16_as_ushort(__float2bfloat16_rn(v.x));
    unsigned short h1 = __bfloat16_as_ushort(__float2bfloat16_rn(v.y));
    unsigned short h2 = __bfloat16_as_ushort(__float2bfloat16_rn(v.z));
    unsigned short h3 = __bfloat16_as_ushort(__float2bfloat16_rn(v.w));
    uint2 r;
    r.x = h0 | ((uint32_t)h1 << 16);
    r.y = h2 | ((uint32_t)h3 << 16);
    return r;
}

// ---------------------------------------------------------------------------
__global__ void prep_kernel(const float* __restrict__ cb) {
    int gr = blockIdx.x * blockDim.x + threadIdx.x;   // 0..8191
    if (gr >= QSTAGES * KCODES) return;
    int stage = gr >> 10, row = gr & 1023;
    int tile = row >> 6, r = row & 63;
    const float4* src = (const float4*)(cb + (size_t)gr * DDIM);
    unsigned char* base = g_cbs + (size_t)(stage * NTILES + tile) * B_TILE_BYTES;
    #pragma unroll 4
    for (int c4 = 0; c4 < 32; c4++) {
        uint2 H = pack_bf16x4(src[c4]);
        uint32_t so = (uint32_t)r * 256 + (uint32_t)(((c4 >> 1) ^ (r & 7)) * 16)
                    + (uint32_t)((c4 & 1) * 8);
        *(uint2*)(base + so) = H;
    }
}

// ---------------------------------------------------------------------------
__global__ void c2_kernel(const float* __restrict__ cb) {
    int warp = (blockIdx.x * blockDim.x + threadIdx.x) >> 5;
    int lane = threadIdx.x & 31;
    const float4* row = (const float4*)(cb + (size_t)warp * DDIM);
    float4 v = row[lane];
    float s = v.x * v.x + v.y * v.y + v.z * v.z + v.w * v.w;
    #pragma unroll
    for (int o = 16; o > 0; o >>= 1) s += __shfl_down_sync(0xffffffffu, s, o);
    if (lane == 0) g_c2[warp] = s;
}

// ---------------------------------------------------------------------------
extern __shared__ char sm[];

__global__ __launch_bounds__(NTHREADS, 1)
void stage_kernel(const float* __restrict__ x,
                  const float* __restrict__ cb_all,
                  float* __restrict__ out,
                  int stage, int is_last) {
    const uint32_t smb = smem_u32(sm);
    const int tid = threadIdx.x, wid = tid >> 5, lid = tid & 31;
    const int tok0 = blockIdx.x * BM;
    const int warpM = wid & 7, warpN = wid >> 3;   // 8 x 2 warp grid
    const float*  src = (stage == 0) ? x : (const float*)g_res;
    const float*  cbf = cb_all + (size_t)stage * KCODES * DDIM;
    const float*  c2  = g_c2 + stage * KCODES;

    int*   cand   = (int*)(sm + CAND_OFF);
    int*   chosen = (int*)(sm + CHOSEN_OFF);
    float* psums  = (float*)(sm + PSUM_OFF);

    // ---- preload B tiles 0,1 ----
    const unsigned char* gcb = g_cbs + (size_t)(stage * NTILES) * B_TILE_BYTES;
    {
        uint32_t b0 = smb + B_OFF, b1 = smb + B_OFF + B_TILE_BYTES;
        #pragma unroll
        for (int k = 0; k < 2; k++) {
            int u = tid + k * NTHREADS;
            cp16(b0 + (uint32_t)u * 16, gcb + (size_t)u * 16);
        }
        cp_commit();
        #pragma unroll
        for (int k = 0; k < 2; k++) {
            int u = tid + k * NTHREADS;
            cp16(b1 + (uint32_t)u * 16, gcb + B_TILE_BYTES + (size_t)u * 16);
        }
        cp_commit();
    }

    // ---- A: residual -> bf16 plane in swizzled smem ----
    {
        const float4* s4 = (const float4*)src + (size_t)tok0 * 32;
        #pragma unroll
        for (int k = 0; k < 8; k++) {
            int f = tid + k * NTHREADS;
            int r = f >> 5, c4 = f & 31;
            uint2 H = pack_bf16x4(s4[f]);
            uint32_t so = (uint32_t)r * 256 + (uint32_t)(((c4 >> 1) ^ (r & 7)) * 16)
                        + (uint32_t)((c4 & 1) * 8);
            *(uint2*)(sm + A_OFF + so) = H;
        }
    }
    __syncthreads();

    // lane addressing
    const int arow = warpM * 16 + (lid & 15);
    const uint32_t aRowByte = (uint32_t)arow * 256;
    const uint32_t aRx = (uint32_t)(arow & 7);
    const uint32_t aKh = (uint32_t)(lid >> 4);
    uint32_t bRowByte[2], bRx[2];
    #pragma unroll
    for (int pi = 0; pi < 2; pi++) {
        int row = warpN * 32 + pi * 16 + ((lid >> 4) << 3) + (lid & 7);
        bRowByte[pi] = (uint32_t)row * 256;
        bRx[pi] = (uint32_t)(row & 7);
    }
    const uint32_t bKh = (uint32_t)((lid >> 3) & 1);

    float v1[2], v2[2], v3[2]; int i1[2], i2[2], i3[2];
    #pragma unroll
    for (int h = 0; h < 2; h++) {
        v1[h] = 3.4e38f; v2[h] = 3.4e38f; v3[h] = 3.4e38f;
        i1[h] = 0; i2[h] = 0; i3[h] = 0;
    }

    for (int t = 0; t < NTILES; t++) {
        if (t < NTILES - 1) cp_wait<1>(); else cp_wait<0>();
        __syncthreads();
        if (t + 2 < NTILES) {
            uint32_t bb = smb + B_OFF + (uint32_t)((t + 2) % 3) * B_TILE_BYTES;
            const unsigned char* gs = gcb + (size_t)(t + 2) * B_TILE_BYTES;
            #pragma unroll
            for (int k = 0; k < 2; k++) {
                int u = tid + k * NTHREADS;
                cp16(bb + (uint32_t)u * 16, gs + (size_t)u * 16);
            }
            cp_commit();
        }
        const uint32_t bbuf = smb + B_OFF + (uint32_t)(t % 3) * B_TILE_BYTES;

        float acc[4][4];
        #pragma unroll
        for (int ni = 0; ni < 4; ni++)
            #pragma unroll
            for (int q = 0; q < 4; q++) acc[ni][q] = 0.f;

        #pragma unroll
        for (int k8 = 0; k8 < 8; k8++) {
            const uint32_t ku = (uint32_t)(2 * k8);
            uint32_t a[4];
            {
                uint32_t addr = smb + A_OFF + aRowByte + (((ku + aKh) ^ aRx) << 4);
                ldsm4(a[0], a[1], a[2], a[3], addr);
            }
            uint32_t b[2][4];
            #pragma unroll
            for (int pi = 0; pi < 2; pi++) {
                uint32_t addr = bbuf + bRowByte[pi] + (((ku + bKh) ^ bRx[pi]) << 4);
                ldsm4(b[pi][0], b[pi][1], b[pi][2], b[pi][3], addr);
            }
            #pragma unroll
            for (int pi = 0; pi < 2; pi++) {
                mma16816(acc[pi*2][0], acc[pi*2][1], acc[pi*2][2], acc[pi*2][3],
                         a[0], a[1], a[2], a[3], b[pi][0], b[pi][1]);
                mma16816(acc[pi*2+1][0], acc[pi*2+1][1], acc[pi*2+1][2], acc[pi*2+1][3],
                         a[0], a[1], a[2], a[3], b[pi][2], b[pi][3]);
            }
        }

        const int codebase = t * NTILE + warpN * 32;
        #pragma unroll
        for (int ni = 0; ni < 4; ni++) {
            int code0 = codebase + ni * 8 + (lid & 3) * 2;
            float2 cc = __ldg((const float2*)(c2 + code0));
            #pragma unroll
            for (int h = 0; h < 2; h++) {
                float d0 = cc.x - 2.f * acc[ni][h * 2];
                float d1 = cc.y - 2.f * acc[ni][h * 2 + 1];
                ins3(d0, code0,     v1[h], i1[h], v2[h], i2[h], v3[h], i3[h]);
                ins3(d1, code0 + 1, v1[h], i1[h], v2[h], i2[h], v3[h], i3[h]);
            }
        }
        __syncthreads();
    }

    // candidates per token: cand[token*24 + warpN*12 + (lid&3)*3 + q]
    #pragma unroll
    for (int h = 0; h < 2; h++) {
        int row = warpM * 16 + h * 8 + (lid >> 2);
        int* myc = cand + row * 24 + warpN * 12 + (lid & 3) * 3;
        myc[0] = i1[h]; myc[1] = i2[h]; myc[2] = i3[h];
    }
    __syncthreads();

    // ---- stage fp32 residual into smem (overlay A+B region) ----
    float4* smres4 = (float4*)(sm + RES_OFF);
    {
        const float4* s4 = (const float4*)src + (size_t)tok0 * 32;
        #pragma unroll
        for (int k = 0; k < 8; k++) {
            int f = tid + k * NTHREADS;
            smres4[f] = s4[f];
        }
    }
    __syncthreads();

    // ---- warp-cooperative exact rescue: warp w -> tokens w*8..w*8+7 ----
    {
        const int tk8 = wid * 8;
        float bv[8]; int bi[8];
        #pragma unroll
        for (int tk = 0; tk < 8; tk++) { bv[tk] = 3.4e38f; bi[tk] = 0x7fffffff; }

        for (int q = 0; q < 24; q++) {
            float part[8]; int jj[8];
            #pragma unroll
            for (int tk = 0; tk < 8; tk++) {
                int token = tk8 + tk;
                int j = cand[token * 24 + q];           // LDS broadcast
                jj[tk] = j;
                float4 cv = __ldg((const float4*)(cbf + (size_t)j * DDIM) + lid);
                float4 rv = smres4[token * 32 + lid];
                part[tk] = cv.x * rv.x + cv.y * rv.y + cv.z * rv.z + cv.w * rv.w;
            }
            #pragma unroll
            for (int tk = 0; tk < 8; tk++) {
                float s = part[tk];
                #pragma unroll
                for (int o = 16; o > 0; o >>= 1)
                    s += __shfl_xor_sync(0xffffffffu, s, o);
                float dd = __ldg(&c2[jj[tk]]) - 2.f * s;
                if (dless(dd, jj[tk], bv[tk], bi[tk])) { bv[tk] = dd; bi[tk] = jj[tk]; }
            }
        }
        if (lid == 0) {
            #pragma unroll
            for (int tk = 0; tk < 8; tk++) {
                int token = tk8 + tk;
                chosen[token] = bi[tk];
                out[(size_t)(tok0 + token) * QSTAGES + stage] = (float)bi[tk];
            }
        }
    }
    __syncthreads();

    // ---- residual update + commit partial + optional quantized (fp32 exact) ----
    const float4* cb4 = (const float4*)cbf;
    float4*       res4 = (float4*)g_res + (size_t)tok0 * 32;
    const float4* x4   = (const float4*)x + (size_t)tok0 * 32;
    float4*       q4   = (float4*)(out + (size_t)TOKENS * QSTAGES) + (size_t)tok0 * 32;

    float psum = 0.f;
    #pragma unroll
    for (int k = 0; k < 8; k++) {
        int f = tid + k * NTHREADS;
        int tk = f >> 5, d4 = f & 31;
        float4 rv = smres4[f];
        float4 cv = cb4[(size_t)chosen[tk] * 32 + d4];
        float4 nv = make_float4(rv.x - cv.x, rv.y - cv.y, rv.z - cv.z, rv.w - cv.w);
        res4[tk * 32 + d4] = nv;
        psum += nv.x * nv.x + nv.y * nv.y + nv.z * nv.z + nv.w * nv.w;
        if (is_last) {
            float4 xv = x4[f];
            q4[tk * 32 + d4] = make_float4(xv.x - nv.x, xv.y - nv.y,
                                           xv.z - nv.z, xv.w - nv.w);
        }
    }
    #pragma unroll
    for (int o = 16; o > 0; o >>= 1) psum += __shfl_down_sync(0xffffffffu, psum, o);
    __syncthreads();
    if (lid == 0) psums[wid] = psum;
    __syncthreads();
    if (tid == 0) {
        float s = 0.f;
        #pragma unroll
        for (int w2 = 0; w2 < 16; w2++) s += psums[w2];
        g_partial[stage * NBLOCKS + blockIdx.x] = s;
    }
}

// ---------------------------------------------------------------------------
__global__ void finish_kernel(float* __restrict__ out) {
    int q = threadIdx.x;
    if (q < QSTAGES) {
        float s = 0.f;
        for (int b = 0; b < NBLOCKS; b++) s += g_partial[q * NBLOCKS + b];
        out[(size_t)TOKENS * QSTAGES + (size_t)TOKENS * DDIM + q] =
            s / (float)(TOKENS * DDIM);
    }
}

extern "C" void kernel_launch(void* const* d_in, const int* in_sizes, int n_in,
                              void* d_out, int out_size) {
    const float* x  = (const float*)d_in[0];
    const float* cb = (const float*)d_in[1];
    float* out = (float*)d_out;

    cudaFuncSetAttribute(stage_kernel,
                         cudaFuncAttributeMaxDynamicSharedMemorySize, SMEM_TOTAL);

    prep_kernel<<<64, 128>>>(cb);
    c2_kernel<<<1024, 256>>>(cb);
    for (int s = 0; s < QSTAGES; s++) {
        stage_kernel<<<NBLOCKS, NTHREADS, SMEM_TOTAL>>>(x, cb, out, s,
                                                        (s == QSTAGES - 1) ? 1 : 0);
    }
    finish_kernel<<<1, 32>>>(out);
}

// round 13
// speedup vs baseline: 6.4792x; 1.4868x over previous
#include <cuda_runtime.h>
#include <cuda_bf16.h>
#include <cstdint>

// RVQ: x [16,2048,128] f32, codebooks [8,1024,128] f32
// out (float32): indices [B*N*Q] ++ quantized [B*N*D] ++ commits [Q]
// Core: single-product bf16 HMMA filter + per-lane top-3 + margin-gated
// exact fp32 rescue (typically ~3 candidates/token).

#define TOKENS   32768
#define DDIM     128
#define KCODES   1024
#define QSTAGES  8
#define BM       128
#define NTILE    64
#define NTILES   (KCODES / NTILE)   // 16
#define NTHREADS 512
#define NBLOCKS  (TOKENS / BM)      // 256
#define MARGIN   0.35f

#define A_BYTES      32768   // 128 rows x 256 B (bf16 plane)
#define B_TILE_BYTES 16384
#define A_OFF        0
#define B_OFF        32768   // 3 buffers x 16384 -> ends 81920
#define RES_OFF      0       // fp32 residual overlay (64KB), after mainloop
#define CAND_OFF     81920   // [128][24] int   = 12288
#define CANDV_OFF    94208   // [128][24] float = 12288
#define CCNT_OFF     106496  // [128] int
#define CHOSEN_OFF   107008  // [128] int
#define PSUM_OFF     107520  // [16] float
#define SMEM_TOTAL   107584

__device__ float g_res[TOKENS * DDIM];
__device__ float g_c2[QSTAGES * KCODES];
__device__ float g_partial[QSTAGES * NBLOCKS];
__device__ unsigned char g_cbs[(size_t)QSTAGES * NTILES * B_TILE_BYTES]; // 2MB

// ---------------------------------------------------------------------------
__device__ __forceinline__ void cp16(uint32_t dst, const void* src) {
    asm volatile("cp.async.cg.shared.global [%0], [%1], 16;" :: "r"(dst), "l"(src));
}
__device__ __forceinline__ void cp_commit() { asm volatile("cp.async.commit_group;"); }
template<int N> __device__ __forceinline__ void cp_wait() {
    asm volatile("cp.async.wait_group %0;" :: "n"(N) : "memory");
}
__device__ __forceinline__ uint32_t smem_u32(const void* p) {
    uint32_t a;
    asm("{ .reg .u64 t; cvta.to.shared.u64 t, %1; cvt.u32.u64 %0, t; }" : "=r"(a) : "l"(p));
    return a;
}
__device__ __forceinline__ void ldsm4(uint32_t& r0, uint32_t& r1, uint32_t& r2,
                                      uint32_t& r3, uint32_t addr) {
    asm volatile("ldmatrix.sync.aligned.m8n8.x4.shared.b16 {%0,%1,%2,%3}, [%4];"
                 : "=r"(r0), "=r"(r1), "=r"(r2), "=r"(r3) : "r"(addr));
}
__device__ __forceinline__ void mma16816(float& d0, float& d1, float& d2, float& d3,
                                         uint32_t a0, uint32_t a1, uint32_t a2,
                                         uint32_t a3, uint32_t b0, uint32_t b1) {
    asm volatile(
        "mma.sync.aligned.m16n8k16.row.col.f32.bf16.bf16.f32 "
        "{%0,%1,%2,%3}, {%4,%5,%6,%7}, {%8,%9}, {%0,%1,%2,%3};"
        : "+f"(d0), "+f"(d1), "+f"(d2), "+f"(d3)
        : "r"(a0), "r"(a1), "r"(a2), "r"(a3), "r"(b0), "r"(b1));
}
__device__ __forceinline__ bool dless(float a, int ia, float b, int ib) {
    return a < b || (a == b && ia < ib);
}
__device__ __forceinline__ void ins3(float d, int idx,
                                     float& v1, int& i1, float& v2, int& i2,
                                     float& v3, int& i3) {
    if (d < v3) {
        if (d < v2) {
            v3 = v2; i3 = i2;
            if (d < v1) { v2 = v1; i2 = i1; v1 = d; i1 = idx; }
            else        { v2 = d;  i2 = idx; }
        } else { v3 = d; i3 = idx; }
    }
}
__device__ __forceinline__ uint2 pack_bf16x4(float4 v) {
    unsigned short h0 = __bfloat16_as_ushort(__float2bfloat16_rn(v.x));
    unsigned short h1 = __bfloat16_as_ushort(__float2bfloat16_rn(v.y));
    unsigned short h2 = __bfloat16_as_ushort(__float2bfloat16_rn(v.z));
    unsigned short h3 = __bfloat16_as_ushort(__float2bfloat16_rn(v.w));
    uint2 r;
    r.x = h0 | ((uint32_t)h1 << 16);
    r.y = h2 | ((uint32_t)h3 << 16);
    return r;
}

// ---------------------------------------------------------------------------
__global__ void prep_kernel(const float* __restrict__ cb) {
    int gr = blockIdx.x * blockDim.x + threadIdx.x;   // 0..8191
    if (gr >= QSTAGES * KCODES) return;
    int stage = gr >> 10, row = gr & 1023;
    int tile = row >> 6, r = row & 63;
    const float4* src = (const float4*)(cb + (size_t)gr * DDIM);
    unsigned char* base = g_cbs + (size_t)(stage * NTILES + tile) * B_TILE_BYTES;
    #pragma unroll 4
    for (int c4 = 0; c4 < 32; c4++) {
        uint2 H = pack_bf16x4(src[c4]);
        uint32_t so = (uint32_t)r * 256 + (uint32_t)(((c4 >> 1) ^ (r & 7)) * 16)
                    + (uint32_t)((c4 & 1) * 8);
        *(uint2*)(base + so) = H;
    }
}

// ---------------------------------------------------------------------------
__global__ void c2_kernel(const float* __restrict__ cb) {
    int warp = (blockIdx.x * blockDim.x + threadIdx.x) >> 5;
    int lane = threadIdx.x & 31;
    const float4* row = (const float4*)(cb + (size_t)warp * DDIM);
    float4 v = row[lane];
    float s = v.x * v.x + v.y * v.y + v.z * v.z + v.w * v.w;
    #pragma unroll
    for (int o = 16; o > 0; o >>= 1) s += __shfl_down_sync(0xffffffffu, s, o);
    if (lane == 0) g_c2[warp] = s;
}

// ---------------------------------------------------------------------------
extern __shared__ char sm[];

__global__ __launch_bounds__(NTHREADS, 1)
void stage_kernel(const float* __restrict__ x,
                  const float* __restrict__ cb_all,
                  float* __restrict__ out,
                  int stage, int is_last) {
    const uint32_t smb = smem_u32(sm);
    const int tid = threadIdx.x, wid = tid >> 5, lid = tid & 31;
    const int tok0 = blockIdx.x * BM;
    const int warpM = wid & 7, warpN = wid >> 3;   // 8 x 2 warp grid
    const float*  src = (stage == 0) ? x : (const float*)g_res;
    const float*  cbf = cb_all + (size_t)stage * KCODES * DDIM;
    const float*  c2  = g_c2 + stage * KCODES;

    int*   cand   = (int*)(sm + CAND_OFF);
    float* candv  = (float*)(sm + CANDV_OFF);
    int*   ccnt   = (int*)(sm + CCNT_OFF);
    int*   chosen = (int*)(sm + CHOSEN_OFF);
    float* psums  = (float*)(sm + PSUM_OFF);

    // ---- preload B tiles 0,1 ----
    const unsigned char* gcb = g_cbs + (size_t)(stage * NTILES) * B_TILE_BYTES;
    {
        uint32_t b0 = smb + B_OFF, b1 = smb + B_OFF + B_TILE_BYTES;
        #pragma unroll
        for (int k = 0; k < 2; k++) {
            int u = tid + k * NTHREADS;
            cp16(b0 + (uint32_t)u * 16, gcb + (size_t)u * 16);
        }
        cp_commit();
        #pragma unroll
        for (int k = 0; k < 2; k++) {
            int u = tid + k * NTHREADS;
            cp16(b1 + (uint32_t)u * 16, gcb + B_TILE_BYTES + (size_t)u * 16);
        }
        cp_commit();
    }

    // ---- A: residual -> bf16 plane in swizzled smem ----
    {
        const float4* s4 = (const float4*)src + (size_t)tok0 * 32;
        #pragma unroll
        for (int k = 0; k < 8; k++) {
            int f = tid + k * NTHREADS;
            int r = f >> 5, c4 = f & 31;
            uint2 H = pack_bf16x4(s4[f]);
            uint32_t so = (uint32_t)r * 256 + (uint32_t)(((c4 >> 1) ^ (r & 7)) * 16)
                        + (uint32_t)((c4 & 1) * 8);
            *(uint2*)(sm + A_OFF + so) = H;
        }
    }
    __syncthreads();

    // lane addressing
    const int arow = warpM * 16 + (lid & 15);
    const uint32_t aRowByte = (uint32_t)arow * 256;
    const uint32_t aRx = (uint32_t)(arow & 7);
    const uint32_t aKh = (uint32_t)(lid >> 4);
    uint32_t bRowByte[2], bRx[2];
    #pragma unroll
    for (int pi = 0; pi < 2; pi++) {
        int row = warpN * 32 + pi * 16 + ((lid >> 4) << 3) + (lid & 7);
        bRowByte[pi] = (uint32_t)row * 256;
        bRx[pi] = (uint32_t)(row & 7);
    }
    const uint32_t bKh = (uint32_t)((lid >> 3) & 1);

    float v1[2], v2[2], v3[2]; int i1[2], i2[2], i3[2];
    #pragma unroll
    for (int h = 0; h < 2; h++) {
        v1[h] = 3.4e38f; v2[h] = 3.4e38f; v3[h] = 3.4e38f;
        i1[h] = 0; i2[h] = 0; i3[h] = 0;
    }

    for (int t = 0; t < NTILES; t++) {
        if (t < NTILES - 1) cp_wait<1>(); else cp_wait<0>();
        __syncthreads();
        if (t + 2 < NTILES) {
            uint32_t bb = smb + B_OFF + (uint32_t)((t + 2) % 3) * B_TILE_BYTES;
            const unsigned char* gs = gcb + (size_t)(t + 2) * B_TILE_BYTES;
            #pragma unroll
            for (int k = 0; k < 2; k++) {
                int u = tid + k * NTHREADS;
                cp16(bb + (uint32_t)u * 16, gs + (size_t)u * 16);
            }
            cp_commit();
        }
        const uint32_t bbuf = smb + B_OFF + (uint32_t)(t % 3) * B_TILE_BYTES;

        float acc[4][4];
        #pragma unroll
        for (int ni = 0; ni < 4; ni++)
            #pragma unroll
            for (int q = 0; q < 4; q++) acc[ni][q] = 0.f;

        #pragma unroll
        for (int k8 = 0; k8 < 8; k8++) {
            const uint32_t ku = (uint32_t)(2 * k8);
            uint32_t a[4];
            {
                uint32_t addr = smb + A_OFF + aRowByte + (((ku + aKh) ^ aRx) << 4);
                ldsm4(a[0], a[1], a[2], a[3], addr);
            }
            uint32_t b[2][4];
            #pragma unroll
            for (int pi = 0; pi < 2; pi++) {
                uint32_t addr = bbuf + bRowByte[pi] + (((ku + bKh) ^ bRx[pi]) << 4);
                ldsm4(b[pi][0], b[pi][1], b[pi][2], b[pi][3], addr);
            }
            #pragma unroll
            for (int pi = 0; pi < 2; pi++) {
                mma16816(acc[pi*2][0], acc[pi*2][1], acc[pi*2][2], acc[pi*2][3],
                         a[0], a[1], a[2], a[3], b[pi][0], b[pi][1]);
                mma16816(acc[pi*2+1][0], acc[pi*2+1][1], acc[pi*2+1][2], acc[pi*2+1][3],
                         a[0], a[1], a[2], a[3], b[pi][2], b[pi][3]);
            }
        }

        const int codebase = t * NTILE + warpN * 32;
        #pragma unroll
        for (int ni = 0; ni < 4; ni++) {
            int code0 = codebase + ni * 8 + (lid & 3) * 2;
            float2 cc = __ldg((const float2*)(c2 + code0));
            #pragma unroll
            for (int h = 0; h < 2; h++) {
                float d0 = cc.x - 2.f * acc[ni][h * 2];
                float d1 = cc.y - 2.f * acc[ni][h * 2 + 1];
                ins3(d0, code0,     v1[h], i1[h], v2[h], i2[h], v3[h], i3[h]);
                ins3(d1, code0 + 1, v1[h], i1[h], v2[h], i2[h], v3[h], i3[h]);
            }
        }
        __syncthreads();
    }

    // candidates + approx values per token
    #pragma unroll
    for (int h = 0; h < 2; h++) {
        int row = warpM * 16 + h * 8 + (lid >> 2);
        int base = row * 24 + warpN * 12 + (lid & 3) * 3;
        cand[base + 0] = i1[h]; candv[base + 0] = v1[h];
        cand[base + 1] = i2[h]; candv[base + 1] = v2[h];
        cand[base + 2] = i3[h]; candv[base + 2] = v3[h];
    }
    __syncthreads();

    // ---- stage fp32 residual into smem (overlay A+B region) ----
    float4* smres4 = (float4*)(sm + RES_OFF);
    {
        const float4* s4 = (const float4*)src + (size_t)tok0 * 32;
        #pragma unroll
        for (int k = 0; k < 8; k++) {
            int f = tid + k * NTHREADS;
            smres4[f] = s4[f];
        }
    }
    // ---- margin-gated compaction: one thread per token ----
    if (tid < BM) {
        float bestAv = 3.4e38f;
        #pragma unroll
        for (int q = 0; q < 24; q++) {
            float v = candv[tid * 24 + q];
            if (v < bestAv) bestAv = v;
        }
        float cut = bestAv + MARGIN;
        int n = 0;
        #pragma unroll
        for (int q = 0; q < 24; q++) {
            if (candv[tid * 24 + q] <= cut) {
                cand[tid * 24 + n] = cand[tid * 24 + q];
                n++;
            }
        }
        ccnt[tid] = n;
    }
    __syncthreads();

    // ---- warp-cooperative exact rescue: warp w -> tokens w*8..w*8+7 ----
    {
        const int tk8 = wid * 8;
        #pragma unroll
        for (int tk = 0; tk < 8; tk++) {
            int token = tk8 + tk;
            int n = ccnt[token];                    // warp-uniform broadcast
            float4 rv = smres4[token * 32 + lid];
            float bv = 3.4e38f; int bi = 0x7fffffff;
            for (int q = 0; q < n; q++) {
                int j = cand[token * 24 + q];
                float4 cv = __ldg((const float4*)(cbf + (size_t)j * DDIM) + lid);
                float s = cv.x * rv.x + cv.y * rv.y + cv.z * rv.z + cv.w * rv.w;
                #pragma unroll
                for (int o = 16; o > 0; o >>= 1)
                    s += __shfl_xor_sync(0xffffffffu, s, o);
                float dd = __ldg(&c2[j]) - 2.f * s;
                if (dless(dd, j, bv, bi)) { bv = dd; bi = j; }
            }
            if (lid == 0) {
                chosen[token] = bi;
                out[(size_t)(tok0 + token) * QSTAGES + stage] = (float)bi;
            }
        }
    }
    __syncthreads();

    // ---- residual update + commit partial + optional quantized (fp32 exact) ----
    const float4* cb4 = (const float4*)cbf;
    float4*       res4 = (float4*)g_res + (size_t)tok0 * 32;
    const float4* x4   = (const float4*)x + (size_t)tok0 * 32;
    float4*       q4   = (float4*)(out + (size_t)TOKENS * QSTAGES) + (size_t)tok0 * 32;

    float psum = 0.f;
    #pragma unroll
    for (int k = 0; k < 8; k++) {
        int f = tid + k * NTHREADS;
        int tk = f >> 5, d4 = f & 31;
        float4 rv = smres4[f];
        float4 cv = cb4[(size_t)chosen[tk] * 32 + d4];
        float4 nv = make_float4(rv.x - cv.x, rv.y - cv.y, rv.z - cv.z, rv.w - cv.w);
        res4[tk * 32 + d4] = nv;
        psum += nv.x * nv.x + nv.y * nv.y + nv.z * nv.z + nv.w * nv.w;
        if (is_last) {
            float4 xv = x4[f];
            q4[tk * 32 + d4] = make_float4(xv.x - nv.x, xv.y - nv.y,
                                           xv.z - nv.z, xv.w - nv.w);
        }
    }
    #pragma unroll
    for (int o = 16; o > 0; o >>= 1) psum += __shfl_down_sync(0xffffffffu, psum, o);
    __syncthreads();
    if (lid == 0) psums[wid] = psum;
    __syncthreads();
    if (tid == 0) {
        float s = 0.f;
        #pragma unroll
        for (int w2 = 0; w2 < 16; w2++) s += psums[w2];
        g_partial[stage * NBLOCKS + blockIdx.x] = s;
    }
}

// ---------------------------------------------------------------------------
__global__ void finish_kernel(float* __restrict__ out) {
    int q = threadIdx.x;
    if (q < QSTAGES) {
        float s = 0.f;
        for (int b = 0; b < NBLOCKS; b++) s += g_partial[q * NBLOCKS + b];
        out[(size_t)TOKENS * QSTAGES + (size_t)TOKENS * DDIM + q] =
            s / (float)(TOKENS * DDIM);
    }
}

extern "C" void kernel_launch(void* const* d_in, const int* in_sizes, int n_in,
                              void* d_out, int out_size) {
    const float* x  = (const float*)d_in[0];
    const float* cb = (const float*)d_in[1];
    float* out = (float*)d_out;

    cudaFuncSetAttribute(stage_kernel,
                         cudaFuncAttributeMaxDynamicSharedMemorySize, SMEM_TOTAL);

    prep_kernel<<<64, 128>>>(cb);
    c2_kernel<<<1024, 256>>>(cb);
    for (int s = 0; s < QSTAGES; s++) {
        stage_kernel<<<NBLOCKS, NTHREADS, SMEM_TOTAL>>>(x, cb, out, s,
                                                        (s == QSTAGES - 1) ? 1 : 0);
    }
    finish_kernel<<<1, 32>>>(out);
}

// round 14
// speedup vs baseline: 7.5103x; 1.1591x over previous
#include <cuda_runtime.h>
#include <cuda_fp16.h>
#include <cstdint>

// RVQ: x [16,2048,128] f32, codebooks [8,1024,128] f32
// out (float32): indices [B*N*Q] ++ quantized [B*N+D] ++ commits [Q]
// Core: single-product fp16 HMMA filter + per-lane top-3 + margin-gated
// exact fp32 rescue. BM=64, 2 CTAs/SM for latency overlap.

#define TOKENS   32768
#define DDIM     128
#define KCODES   1024
#define QSTAGES  8
#define BM       64
#define NTILE    64
#define NTILES   (KCODES / NTILE)   // 16
#define NTHREADS 256
#define NBLOCKS  (TOKENS / BM)      // 512
#define MARGIN   0.12f

#define A_BYTES      16384   // 64 rows x 256 B (fp16 plane)
#define B_TILE_BYTES 16384
#define A_OFF        0
#define B_OFF        16384   // 3 buffers x 16384 -> ends 65536
#define RES_OFF      0       // fp32 residual overlay (32KB), after mainloop
#define CAND_OFF     65536   // [64][24] int   = 6144
#define CANDV_OFF    71680   // [64][24] float = 6144
#define CCNT_OFF     77824   // [64] int
#define CHOSEN_OFF   78080   // [64] int
#define PSUM_OFF     78336   // [8] float
#define SMEM_TOTAL   78400

__device__ float g_res[TOKENS * DDIM];
__device__ float g_c2[QSTAGES * KCODES];
__device__ float g_partial[QSTAGES * NBLOCKS];
__device__ unsigned char g_cbs[(size_t)QSTAGES * NTILES * B_TILE_BYTES]; // 2MB

// ---------------------------------------------------------------------------
__device__ __forceinline__ void cp16(uint32_t dst, const void* src) {
    asm volatile("cp.async.cg.shared.global [%0], [%1], 16;" :: "r"(dst), "l"(src));
}
__device__ __forceinline__ void cp_commit() { asm volatile("cp.async.commit_group;"); }
template<int N> __device__ __forceinline__ void cp_wait() {
    asm volatile("cp.async.wait_group %0;" :: "n"(N) : "memory");
}
__device__ __forceinline__ uint32_t smem_u32(const void* p) {
    uint32_t a;
    asm("{ .reg .u64 t; cvta.to.shared.u64 t, %1; cvt.u32.u64 %0, t; }" : "=r"(a) : "l"(p));
    return a;
}
__device__ __forceinline__ void ldsm4(uint32_t& r0, uint32_t& r1, uint32_t& r2,
                                      uint32_t& r3, uint32_t addr) {
    asm volatile("ldmatrix.sync.aligned.m8n8.x4.shared.b16 {%0,%1,%2,%3}, [%4];"
                 : "=r"(r0), "=r"(r1), "=r"(r2), "=r"(r3) : "r"(addr));
}
__device__ __forceinline__ void mma16816(float& d0, float& d1, float& d2, float& d3,
                                         uint32_t a0, uint32_t a1, uint32_t a2,
                                         uint32_t a3, uint32_t b0, uint32_t b1) {
    asm volatile(
        "mma.sync.aligned.m16n8k16.row.col.f32.f16.f16.f32 "
        "{%0,%1,%2,%3}, {%4,%5,%6,%7}, {%8,%9}, {%0,%1,%2,%3};"
        : "+f"(d0), "+f"(d1), "+f"(d2), "+f"(d3)
        : "r"(a0), "r"(a1), "r"(a2), "r"(a3), "r"(b0), "r"(b1));
}
__device__ __forceinline__ bool dless(float a, int ia, float b, int ib) {
    return a < b || (a == b && ia < ib);
}
__device__ __forceinline__ void ins3(float d, int idx,
                                     float& v1, int& i1, float& v2, int& i2,
                                     float& v3, int& i3) {
    if (d < v3) {
        if (d < v2) {
            v3 = v2; i3 = i2;
            if (d < v1) { v2 = v1; i2 = i1; v1 = d; i1 = idx; }
            else        { v2 = d;  i2 = idx; }
        } else { v3 = d; i3 = idx; }
    }
}
__device__ __forceinline__ uint2 pack_h16x4(float4 v) {
    __half h0 = __float2half_rn(v.x), h1 = __float2half_rn(v.y);
    __half h2 = __float2half_rn(v.z), h3 = __float2half_rn(v.w);
    uint2 r;
    r.x = (uint32_t)__half_as_ushort(h0) | ((uint32_t)__half_as_ushort(h1) << 16);
    r.y = (uint32_t)__half_as_ushort(h2) | ((uint32_t)__half_as_ushort(h3) << 16);
    return r;
}

// ---------------------------------------------------------------------------
// prep: codebooks -> fp16 plane in ldmatrix-swizzled 16KB tile images.
// ---------------------------------------------------------------------------
__global__ void prep_kernel(const float* __restrict__ cb) {
    int gr = blockIdx.x * blockDim.x + threadIdx.x;   // 0..8191
    if (gr >= QSTAGES * KCODES) return;
    int stage = gr >> 10, row = gr & 1023;
    int tile = row >> 6, r = row & 63;
    const float4* src = (const float4*)(cb + (size_t)gr * DDIM);
    unsigned char* base = g_cbs + (size_t)(stage * NTILES + tile) * B_TILE_BYTES;
    #pragma unroll 4
    for (int c4 = 0; c4 < 32; c4++) {
        uint2 H = pack_h16x4(src[c4]);
        uint32_t so = (uint32_t)r * 256 + (uint32_t)(((c4 >> 1) ^ (r & 7)) * 16)
                    + (uint32_t)((c4 & 1) * 8);
        *(uint2*)(base + so) = H;
    }
}

// ---------------------------------------------------------------------------
__global__ void c2_kernel(const float* __restrict__ cb) {
    int warp = (blockIdx.x * blockDim.x + threadIdx.x) >> 5;
    int lane = threadIdx.x & 31;
    const float4* row = (const float4*)(cb + (size_t)warp * DDIM);
    float4 v = row[lane];
    float s = v.x * v.x + v.y * v.y + v.z * v.z + v.w * v.w;
    #pragma unroll
    for (int o = 16; o > 0; o >>= 1) s += __shfl_down_sync(0xffffffffu, s, o);
    if (lane == 0) g_c2[warp] = s;
}

// ---------------------------------------------------------------------------
extern __shared__ char sm[];

__global__ __launch_bounds__(NTHREADS, 2)
void stage_kernel(const float* __restrict__ x,
                  const float* __restrict__ cb_all,
                  float* __restrict__ out,
                  int stage, int is_last) {
    const uint32_t smb = smem_u32(sm);
    const int tid = threadIdx.x, wid = tid >> 5, lid = tid & 31;
    const int tok0 = blockIdx.x * BM;
    const int warpM = wid & 3, warpN = wid >> 2;   // 4 x 2 warp grid
    const float*  src = (stage == 0) ? x : (const float*)g_res;
    const float*  cbf = cb_all + (size_t)stage * KCODES * DDIM;
    const float*  c2  = g_c2 + stage * KCODES;

    int*   cand   = (int*)(sm + CAND_OFF);
    float* candv  = (float*)(sm + CANDV_OFF);
    int*   ccnt   = (int*)(sm + CCNT_OFF);
    int*   chosen = (int*)(sm + CHOSEN_OFF);
    float* psums  = (float*)(sm + PSUM_OFF);

    // ---- preload B tiles 0,1 ----
    const unsigned char* gcb = g_cbs + (size_t)(stage * NTILES) * B_TILE_BYTES;
    {
        uint32_t b0 = smb + B_OFF, b1 = smb + B_OFF + B_TILE_BYTES;
        #pragma unroll
        for (int k = 0; k < 4; k++) {
            int u = tid + k * NTHREADS;   // 0..1023
            cp16(b0 + (uint32_t)u * 16, gcb + (size_t)u * 16);
        }
        cp_commit();
        #pragma unroll
        for (int k = 0; k < 4; k++) {
            int u = tid + k * NTHREADS;
            cp16(b1 + (uint32_t)u * 16, gcb + B_TILE_BYTES + (size_t)u * 16);
        }
        cp_commit();
    }

    // ---- A: residual -> fp16 plane in swizzled smem ----
    {
        const float4* s4 = (const float4*)src + (size_t)tok0 * 32;
        #pragma unroll
        for (int k = 0; k < 8; k++) {
            int f = tid + k * NTHREADS;   // 0..2047
            int r = f >> 5, c4 = f & 31;
            uint2 H = pack_h16x4(s4[f]);
            uint32_t so = (uint32_t)r * 256 + (uint32_t)(((c4 >> 1) ^ (r & 7)) * 16)
                        + (uint32_t)((c4 & 1) * 8);
            *(uint2*)(sm + A_OFF + so) = H;
        }
    }
    __syncthreads();

    // lane addressing
    const int arow = warpM * 16 + (lid & 15);
    const uint32_t aRowByte = (uint32_t)arow * 256;
    const uint32_t aRx = (uint32_t)(arow & 7);
    const uint32_t aKh = (uint32_t)(lid >> 4);
    uint32_t bRowByte[2], bRx[2];
    #pragma unroll
    for (int pi = 0; pi < 2; pi++) {
        int row = warpN * 32 + pi * 16 + ((lid >> 4) << 3) + (lid & 7);
        bRowByte[pi] = (uint32_t)row * 256;
        bRx[pi] = (uint32_t)(row & 7);
    }
    const uint32_t bKh = (uint32_t)((lid >> 3) & 1);

    float v1[2], v2[2], v3[2]; int i1[2], i2[2], i3[2];
    #pragma unroll
    for (int h = 0; h < 2; h++) {
        v1[h] = 3.4e38f; v2[h] = 3.4e38f; v3[h] = 3.4e38f;
        i1[h] = 0; i2[h] = 0; i3[h] = 0;
    }

    for (int t = 0; t < NTILES; t++) {
        if (t < NTILES - 1) cp_wait<1>(); else cp_wait<0>();
        __syncthreads();
        if (t + 2 < NTILES) {
            uint32_t bb = smb + B_OFF + (uint32_t)((t + 2) % 3) * B_TILE_BYTES;
            const unsigned char* gs = gcb + (size_t)(t + 2) * B_TILE_BYTES;
            #pragma unroll
            for (int k = 0; k < 4; k++) {
                int u = tid + k * NTHREADS;
                cp16(bb + (uint32_t)u * 16, gs + (size_t)u * 16);
            }
            cp_commit();
        }
        const uint32_t bbuf = smb + B_OFF + (uint32_t)(t % 3) * B_TILE_BYTES;

        float acc[4][4];
        #pragma unroll
        for (int ni = 0; ni < 4; ni++)
            #pragma unroll
            for (int q = 0; q < 4; q++) acc[ni][q] = 0.f;

        #pragma unroll
        for (int k8 = 0; k8 < 8; k8++) {
            const uint32_t ku = (uint32_t)(2 * k8);
            uint32_t a[4];
            {
                uint32_t addr = smb + A_OFF + aRowByte + (((ku + aKh) ^ aRx) << 4);
                ldsm4(a[0], a[1], a[2], a[3], addr);
            }
            uint32_t b[2][4];
            #pragma unroll
            for (int pi = 0; pi < 2; pi++) {
                uint32_t addr = bbuf + bRowByte[pi] + (((ku + bKh) ^ bRx[pi]) << 4);
                ldsm4(b[pi][0], b[pi][1], b[pi][2], b[pi][3], addr);
            }
            #pragma unroll
            for (int pi = 0; pi < 2; pi++) {
                mma16816(acc[pi*2][0], acc[pi*2][1], acc[pi*2][2], acc[pi*2][3],
                         a[0], a[1], a[2], a[3], b[pi][0], b[pi][1]);
                mma16816(acc[pi*2+1][0], acc[pi*2+1][1], acc[pi*2+1][2], acc[pi*2+1][3],
                         a[0], a[1], a[2], a[3], b[pi][2], b[pi][3]);
            }
        }

        const int codebase = t * NTILE + warpN * 32;
        #pragma unroll
        for (int ni = 0; ni < 4; ni++) {
            int code0 = codebase + ni * 8 + (lid & 3) * 2;
            float2 cc = __ldg((const float2*)(c2 + code0));
            #pragma unroll
            for (int h = 0; h < 2; h++) {
                float d0 = cc.x - 2.f * acc[ni][h * 2];
                float d1 = cc.y - 2.f * acc[ni][h * 2 + 1];
                ins3(d0, code0,     v1[h], i1[h], v2[h], i2[h], v3[h], i3[h]);
                ins3(d1, code0 + 1, v1[h], i1[h], v2[h], i2[h], v3[h], i3[h]);
            }
        }
        __syncthreads();
    }

    // candidates + approx values per token
    #pragma unroll
    for (int h = 0; h < 2; h++) {
        int row = warpM * 16 + h * 8 + (lid >> 2);
        int base = row * 24 + warpN * 12 + (lid & 3) * 3;
        cand[base + 0] = i1[h]; candv[base + 0] = v1[h];
        cand[base + 1] = i2[h]; candv[base + 1] = v2[h];
        cand[base + 2] = i3[h]; candv[base + 2] = v3[h];
    }
    __syncthreads();

    // ---- stage fp32 residual into smem (overlay A+B region) ----
    float4* smres4 = (float4*)(sm + RES_OFF);
    {
        const float4* s4 = (const float4*)src + (size_t)tok0 * 32;
        #pragma unroll
        for (int k = 0; k < 8; k++) {
            int f = tid + k * NTHREADS;
            smres4[f] = s4[f];
        }
    }
    // ---- margin-gated compaction: one thread per token ----
    if (tid < BM) {
        float bestAv = 3.4e38f;
        #pragma unroll
        for (int q = 0; q < 24; q++) {
            float v = candv[tid * 24 + q];
            if (v < bestAv) bestAv = v;
        }
        float cut = bestAv + MARGIN;
        int n = 0;
        #pragma unroll
        for (int q = 0; q < 24; q++) {
            if (candv[tid * 24 + q] <= cut) {
                cand[tid * 24 + n] = cand[tid * 24 + q];
                n++;
            }
        }
        ccnt[tid] = n;
    }
    __syncthreads();

    // ---- warp-cooperative exact rescue: warp w -> tokens w*8..w*8+7 ----
    {
        const int tk8 = wid * 8;
        #pragma unroll
        for (int tk = 0; tk < 8; tk++) {
            int token = tk8 + tk;
            int n = ccnt[token];
            float4 rv = smres4[token * 32 + lid];
            float bv = 3.4e38f; int bi = 0x7fffffff;
            for (int q = 0; q < n; q++) {
                int j = cand[token * 24 + q];
                float4 cv = __ldg((const float4*)(cbf + (size_t)j * DDIM) + lid);
                float s = cv.x * rv.x + cv.y * rv.y + cv.z * rv.z + cv.w * rv.w;
                #pragma unroll
                for (int o = 16; o > 0; o >>= 1)
                    s += __shfl_xor_sync(0xffffffffu, s, o);
                float dd = __ldg(&c2[j]) - 2.f * s;
                if (dless(dd, j, bv, bi)) { bv = dd; bi = j; }
            }
            if (lid == 0) {
                chosen[token] = bi;
                out[(size_t)(tok0 + token) * QSTAGES + stage] = (float)bi;
            }
        }
    }
    __syncthreads();

    // ---- residual update + commit partial + optional quantized (fp32 exact) ----
    const float4* cb4 = (const float4*)cbf;
    float4*       res4 = (float4*)g_res + (size_t)tok0 * 32;
    const float4* x4   = (const float4*)x + (size_t)tok0 * 32;
    float4*       q4   = (float4*)(out + (size_t)TOKENS * QSTAGES) + (size_t)tok0 * 32;

    float psum = 0.f;
    #pragma unroll
    for (int k = 0; k < 8; k++) {
        int f = tid + k * NTHREADS;
        int tk = f >> 5, d4 = f & 31;
        float4 rv = smres4[f];
        float4 cv = cb4[(size_t)chosen[tk] * 32 + d4];
        float4 nv = make_float4(rv.x - cv.x, rv.y - cv.y, rv.z - cv.z, rv.w - cv.w);
        res4[tk * 32 + d4] = nv;
        psum += nv.x * nv.x + nv.y * nv.y + nv.z * nv.z + nv.w * nv.w;
        if (is_last) {
            float4 xv = x4[f];
            q4[tk * 32 + d4] = make_float4(xv.x - nv.x, xv.y - nv.y,
                                           xv.z - nv.z, xv.w - nv.w);
        }
    }
    #pragma unroll
    for (int o = 16; o > 0; o >>= 1) psum += __shfl_down_sync(0xffffffffu, psum, o);
    __syncthreads();
    if (lid == 0) psums[wid] = psum;
    __syncthreads();
    if (tid == 0) {
        float s = 0.f;
        #pragma unroll
        for (int w2 = 0; w2 < 8; w2++) s += psums[w2];
        g_partial[stage * NBLOCKS + blockIdx.x] = s;
    }
}

// ---------------------------------------------------------------------------
__global__ void finish_kernel(float* __restrict__ out) {
    int q = threadIdx.x;
    if (q < QSTAGES) {
        float s = 0.f;
        for (int b = 0; b < NBLOCKS; b++) s += g_partial[q * NBLOCKS + b];
        out[(size_t)TOKENS * QSTAGES + (size_t)TOKENS * DDIM + q] =
            s / (float)(TOKENS * DDIM);
    }
}

extern "C" void kernel_launch(void* const* d_in, const int* in_sizes, int n_in,
                              void* d_out, int out_size) {
    const float* x  = (const float*)d_in[0];
    const float* cb = (const float*)d_in[1];
    float* out = (float*)d_out;

    cudaFuncSetAttribute(stage_kernel,
                         cudaFuncAttributeMaxDynamicSharedMemorySize, SMEM_TOTAL);

    prep_kernel<<<64, 128>>>(cb);
    c2_kernel<<<1024, 256>>>(cb);
    for (int s = 0; s < QSTAGES; s++) {
        stage_kernel<<<NBLOCKS, NTHREADS, SMEM_TOTAL>>>(x, cb, out, s,
                                                        (s == QSTAGES - 1) ? 1 : 0);
    }
    finish_kernel<<<1, 32>>>(out);
}

// round 15
// speedup vs baseline: 7.7429x; 1.0310x over previous
#include <cuda_runtime.h>
#include <cuda_fp16.h>
#include <cstdint>

// RVQ: x [16,2048,128] f32, codebooks [8,1024,128] f32
// out (float32): indices [B*N*Q] ++ quantized [B*N*D] ++ commits [Q]
// Core: single-product fp16 HMMA filter (A registerized across tiles) +
// per-lane top-3 + margin-gated exact fp32 rescue. BM=64, 2 CTAs/SM.

#define TOKENS   32768
#define DDIM     128
#define KCODES   1024
#define QSTAGES  8
#define BM       64
#define NTILE    64
#define NTILES   (KCODES / NTILE)   // 16
#define NTHREADS 256
#define NBLOCKS  (TOKENS / BM)      // 512
#define MARGIN   0.12f

#define A_BYTES      16384   // 64 rows x 256 B (fp16 plane)
#define B_TILE_BYTES 16384
#define A_OFF        0
#define B_OFF        16384   // 3 buffers x 16384 -> ends 65536
#define RES_OFF      0       // fp32 residual overlay (32KB), after mainloop
#define CAND_OFF     65536   // [64][24] int   = 6144
#define CANDV_OFF    71680   // [64][24] float = 6144
#define CCNT_OFF     77824   // [64] int
#define CHOSEN_OFF   78080   // [64] int
#define PSUM_OFF     78336   // [8] float
#define SMEM_TOTAL   78400

__device__ float g_res[TOKENS * DDIM];
__device__ float g_c2[QSTAGES * KCODES];
__device__ float g_partial[QSTAGES * NBLOCKS];
__device__ unsigned char g_cbs[(size_t)QSTAGES * NTILES * B_TILE_BYTES]; // 2MB

// ---------------------------------------------------------------------------
__device__ __forceinline__ void cp16(uint32_t dst, const void* src) {
    asm volatile("cp.async.cg.shared.global [%0], [%1], 16;" :: "r"(dst), "l"(src));
}
__device__ __forceinline__ void cp_commit() { asm volatile("cp.async.commit_group;"); }
template<int N> __device__ __forceinline__ void cp_wait() {
    asm volatile("cp.async.wait_group %0;" :: "n"(N) : "memory");
}
__device__ __forceinline__ uint32_t smem_u32(const void* p) {
    uint32_t a;
    asm("{ .reg .u64 t; cvta.to.shared.u64 t, %1; cvt.u32.u64 %0, t; }" : "=r"(a) : "l"(p));
    return a;
}
__device__ __forceinline__ void ldsm4(uint32_t& r0, uint32_t& r1, uint32_t& r2,
                                      uint32_t& r3, uint32_t addr) {
    asm volatile("ldmatrix.sync.aligned.m8n8.x4.shared.b16 {%0,%1,%2,%3}, [%4];"
                 : "=r"(r0), "=r"(r1), "=r"(r2), "=r"(r3) : "r"(addr));
}
__device__ __forceinline__ void mma16816(float& d0, float& d1, float& d2, float& d3,
                                         uint32_t a0, uint32_t a1, uint32_t a2,
                                         uint32_t a3, uint32_t b0, uint32_t b1) {
    asm volatile(
        "mma.sync.aligned.m16n8k16.row.col.f32.f16.f16.f32 "
        "{%0,%1,%2,%3}, {%4,%5,%6,%7}, {%8,%9}, {%0,%1,%2,%3};"
        : "+f"(d0), "+f"(d1), "+f"(d2), "+f"(d3)
        : "r"(a0), "r"(a1), "r"(a2), "r"(a3), "r"(b0), "r"(b1));
}
__device__ __forceinline__ bool dless(float a, int ia, float b, int ib) {
    return a < b || (a == b && ia < ib);
}
__device__ __forceinline__ void ins3(float d, int idx,
                                     float& v1, int& i1, float& v2, int& i2,
                                     float& v3, int& i3) {
    if (d < v3) {
        if (d < v2) {
            v3 = v2; i3 = i2;
            if (d < v1) { v2 = v1; i2 = i1; v1 = d; i1 = idx; }
            else        { v2 = d;  i2 = idx; }
        } else { v3 = d; i3 = idx; }
    }
}
__device__ __forceinline__ uint2 pack_h16x4(float4 v) {
    __half h0 = __float2half_rn(v.x), h1 = __float2half_rn(v.y);
    __half h2 = __float2half_rn(v.z), h3 = __float2half_rn(v.w);
    uint2 r;
    r.x = (uint32_t)__half_as_ushort(h0) | ((uint32_t)__half_as_ushort(h1) << 16);
    r.y = (uint32_t)__half_as_ushort(h2) | ((uint32_t)__half_as_ushort(h3) << 16);
    return r;
}

// ---------------------------------------------------------------------------
__global__ void prep_kernel(const float* __restrict__ cb) {
    int gr = blockIdx.x * blockDim.x + threadIdx.x;   // 0..8191
    if (gr >= QSTAGES * KCODES) return;
    int stage = gr >> 10, row = gr & 1023;
    int tile = row >> 6, r = row & 63;
    const float4* src = (const float4*)(cb + (size_t)gr * DDIM);
    unsigned char* base = g_cbs + (size_t)(stage * NTILES + tile) * B_TILE_BYTES;
    #pragma unroll 4
    for (int c4 = 0; c4 < 32; c4++) {
        uint2 H = pack_h16x4(src[c4]);
        uint32_t so = (uint32_t)r * 256 + (uint32_t)(((c4 >> 1) ^ (r & 7)) * 16)
                    + (uint32_t)((c4 & 1) * 8);
        *(uint2*)(base + so) = H;
    }
}

// ---------------------------------------------------------------------------
__global__ void c2_kernel(const float* __restrict__ cb) {
    int warp = (blockIdx.x * blockDim.x + threadIdx.x) >> 5;
    int lane = threadIdx.x & 31;
    const float4* row = (const float4*)(cb + (size_t)warp * DDIM);
    float4 v = row[lane];
    float s = v.x * v.x + v.y * v.y + v.z * v.z + v.w * v.w;
    #pragma unroll
    for (int o = 16; o > 0; o >>= 1) s += __shfl_down_sync(0xffffffffu, s, o);
    if (lane == 0) g_c2[warp] = s;
}

// ---------------------------------------------------------------------------
extern __shared__ char sm[];

__global__ __launch_bounds__(NTHREADS, 2)
void stage_kernel(const float* __restrict__ x,
                  const float* __restrict__ cb_all,
                  float* __restrict__ out,
                  int stage, int is_last) {
    const uint32_t smb = smem_u32(sm);
    const int tid = threadIdx.x, wid = tid >> 5, lid = tid & 31;
    const int tok0 = blockIdx.x * BM;
    const int warpM = wid & 3, warpN = wid >> 2;   // 4 x 2 warp grid
    const float*  src = (stage == 0) ? x : (const float*)g_res;
    const float*  cbf = cb_all + (size_t)stage * KCODES * DDIM;
    const float*  c2  = g_c2 + stage * KCODES;

    int*   cand   = (int*)(sm + CAND_OFF);
    float* candv  = (float*)(sm + CANDV_OFF);
    int*   ccnt   = (int*)(sm + CCNT_OFF);
    int*   chosen = (int*)(sm + CHOSEN_OFF);
    float* psums  = (float*)(sm + PSUM_OFF);

    // ---- preload B tiles 0,1 ----
    const unsigned char* gcb = g_cbs + (size_t)(stage * NTILES) * B_TILE_BYTES;
    {
        uint32_t b0 = smb + B_OFF, b1 = smb + B_OFF + B_TILE_BYTES;
        #pragma unroll
        for (int k = 0; k < 4; k++) {
            int u = tid + k * NTHREADS;   // 0..1023
            cp16(b0 + (uint32_t)u * 16, gcb + (size_t)u * 16);
        }
        cp_commit();
        #pragma unroll
        for (int k = 0; k < 4; k++) {
            int u = tid + k * NTHREADS;
            cp16(b1 + (uint32_t)u * 16, gcb + B_TILE_BYTES + (size_t)u * 16);
        }
        cp_commit();
    }

    // ---- A: residual -> fp16 plane in swizzled smem ----
    {
        const float4* s4 = (const float4*)src + (size_t)tok0 * 32;
        #pragma unroll
        for (int k = 0; k < 8; k++) {
            int f = tid + k * NTHREADS;   // 0..2047
            int r = f >> 5, c4 = f & 31;
            uint2 H = pack_h16x4(s4[f]);
            uint32_t so = (uint32_t)r * 256 + (uint32_t)(((c4 >> 1) ^ (r & 7)) * 16)
                        + (uint32_t)((c4 & 1) * 8);
            *(uint2*)(sm + A_OFF + so) = H;
        }
    }
    __syncthreads();

    // ---- registerize A fragments for this warp's 16 rows (all 8 k-steps) ----
    const int arow = warpM * 16 + (lid & 15);
    const uint32_t aRowByte = (uint32_t)arow * 256;
    const uint32_t aRx = (uint32_t)(arow & 7);
    const uint32_t aKh = (uint32_t)(lid >> 4);
    uint32_t aH[8][4];
    #pragma unroll
    for (int k8 = 0; k8 < 8; k8++) {
        uint32_t addr = smb + A_OFF + aRowByte
                      + ((((uint32_t)(2 * k8) + aKh) ^ aRx) << 4);
        ldsm4(aH[k8][0], aH[k8][1], aH[k8][2], aH[k8][3], addr);
    }

    // B lane addressing
    uint32_t bRowByte[2], bRx[2];
    #pragma unroll
    for (int pi = 0; pi < 2; pi++) {
        int row = warpN * 32 + pi * 16 + ((lid >> 4) << 3) + (lid & 7);
        bRowByte[pi] = (uint32_t)row * 256;
        bRx[pi] = (uint32_t)(row & 7);
    }
    const uint32_t bKh = (uint32_t)((lid >> 3) & 1);

    float v1[2], v2[2], v3[2]; int i1[2], i2[2], i3[2];
    #pragma unroll
    for (int h = 0; h < 2; h++) {
        v1[h] = 3.4e38f; v2[h] = 3.4e38f; v3[h] = 3.4e38f;
        i1[h] = 0; i2[h] = 0; i3[h] = 0;
    }

    for (int t = 0; t < NTILES; t++) {
        if (t < NTILES - 1) cp_wait<1>(); else cp_wait<0>();
        __syncthreads();   // tile t data visible to all; all warps past tile t-1
        // prefetch tile t+2 into buffer (t+2)%3 == (t-1+3)%3 whose last read
        // was tile t-1 compute (ordered by the barrier above)
        if (t + 2 < NTILES) {
            uint32_t bb = smb + B_OFF + (uint32_t)((t + 2) % 3) * B_TILE_BYTES;
            const unsigned char* gs = gcb + (size_t)(t + 2) * B_TILE_BYTES;
            #pragma unroll
            for (int k = 0; k < 4; k++) {
                int u = tid + k * NTHREADS;
                cp16(bb + (uint32_t)u * 16, gs + (size_t)u * 16);
            }
            cp_commit();
        }
        const uint32_t bbuf = smb + B_OFF + (uint32_t)(t % 3) * B_TILE_BYTES;

        float acc[4][4];
        #pragma unroll
        for (int ni = 0; ni < 4; ni++)
            #pragma unroll
            for (int q = 0; q < 4; q++) acc[ni][q] = 0.f;

        #pragma unroll
        for (int k8 = 0; k8 < 8; k8++) {
            const uint32_t ku = (uint32_t)(2 * k8);
            uint32_t b[2][4];
            #pragma unroll
            for (int pi = 0; pi < 2; pi++) {
                uint32_t addr = bbuf + bRowByte[pi] + (((ku + bKh) ^ bRx[pi]) << 4);
                ldsm4(b[pi][0], b[pi][1], b[pi][2], b[pi][3], addr);
            }
            #pragma unroll
            for (int pi = 0; pi < 2; pi++) {
                mma16816(acc[pi*2][0], acc[pi*2][1], acc[pi*2][2], acc[pi*2][3],
                         aH[k8][0], aH[k8][1], aH[k8][2], aH[k8][3],
                         b[pi][0], b[pi][1]);
                mma16816(acc[pi*2+1][0], acc[pi*2+1][1], acc[pi*2+1][2], acc[pi*2+1][3],
                         aH[k8][0], aH[k8][1], aH[k8][2], aH[k8][3],
                         b[pi][2], b[pi][3]);
            }
        }

        const int codebase = t * NTILE + warpN * 32;
        #pragma unroll
        for (int ni = 0; ni < 4; ni++) {
            int code0 = codebase + ni * 8 + (lid & 3) * 2;
            float2 cc = __ldg((const float2*)(c2 + code0));
            #pragma unroll
            for (int h = 0; h < 2; h++) {
                float d0 = cc.x - 2.f * acc[ni][h * 2];
                float d1 = cc.y - 2.f * acc[ni][h * 2 + 1];
                ins3(d0, code0,     v1[h], i1[h], v2[h], i2[h], v3[h], i3[h]);
                ins3(d1, code0 + 1, v1[h], i1[h], v2[h], i2[h], v3[h], i3[h]);
            }
        }
        // no end-of-tile barrier: next iteration's top barrier provides the
        // ordering before buffer reuse
    }

    // candidates + approx values per token
    #pragma unroll
    for (int h = 0; h < 2; h++) {
        int row = warpM * 16 + h * 8 + (lid >> 2);
        int base = row * 24 + warpN * 12 + (lid & 3) * 3;
        cand[base + 0] = i1[h]; candv[base + 0] = v1[h];
        cand[base + 1] = i2[h]; candv[base + 1] = v2[h];
        cand[base + 2] = i3[h]; candv[base + 2] = v3[h];
    }
    __syncthreads();

    // ---- stage fp32 residual into smem (overlay A+B region) ----
    float4* smres4 = (float4*)(sm + RES_OFF);
    {
        const float4* s4 = (const float4*)src + (size_t)tok0 * 32;
        #pragma unroll
        for (int k = 0; k < 8; k++) {
            int f = tid + k * NTHREADS;
            smres4[f] = s4[f];
        }
    }
    // ---- margin-gated compaction: one thread per token ----
    if (tid < BM) {
        float bestAv = 3.4e38f;
        #pragma unroll
        for (int q = 0; q < 24; q++) {
            float v = candv[tid * 24 + q];
            if (v < bestAv) bestAv = v;
        }
        float cut = bestAv + MARGIN;
        int n = 0;
        #pragma unroll
        for (int q = 0; q < 24; q++) {
            if (candv[tid * 24 + q] <= cut) {
                cand[tid * 24 + n] = cand[tid * 24 + q];
                n++;
            }
        }
        ccnt[tid] = n;
    }
    __syncthreads();

    // ---- warp-cooperative exact rescue: warp w -> tokens w*8..w*8+7 ----
    {
        const int tk8 = wid * 8;
        #pragma unroll
        for (int tk = 0; tk < 8; tk++) {
            int token = tk8 + tk;
            int n = ccnt[token];
            float4 rv = smres4[token * 32 + lid];
            float bv = 3.4e38f; int bi = 0x7fffffff;
            for (int q = 0; q < n; q++) {
                int j = cand[token * 24 + q];
                float4 cv = __ldg((const float4*)(cbf + (size_t)j * DDIM) + lid);
                float s = cv.x * rv.x + cv.y * rv.y + cv.z * rv.z + cv.w * rv.w;
                #pragma unroll
                for (int o = 16; o > 0; o >>= 1)
                    s += __shfl_xor_sync(0xffffffffu, s, o);
                float dd = __ldg(&c2[j]) - 2.f * s;
                if (dless(dd, j, bv, bi)) { bv = dd; bi = j; }
            }
            if (lid == 0) {
                chosen[token] = bi;
                out[(size_t)(tok0 + token) * QSTAGES + stage] = (float)bi;
            }
        }
    }
    __syncthreads();

    // ---- residual update + commit partial + optional quantized (fp32 exact) ----
    const float4* cb4 = (const float4*)cbf;
    float4*       res4 = (float4*)g_res + (size_t)tok0 * 32;
    const float4* x4   = (const float4*)x + (size_t)tok0 * 32;
    float4*       q4   = (float4*)(out + (size_t)TOKENS * QSTAGES) + (size_t)tok0 * 32;

    float psum = 0.f;
    #pragma unroll
    for (int k = 0; k < 8; k++) {
        int f = tid + k * NTHREADS;
        int tk = f >> 5, d4 = f & 31;
        float4 rv = smres4[f];
        float4 cv = cb4[(size_t)chosen[tk] * 32 + d4];
        float4 nv = make_float4(rv.x - cv.x, rv.y - cv.y, rv.z - cv.z, rv.w - cv.w);
        res4[tk * 32 + d4] = nv;
        psum += nv.x * nv.x + nv.y * nv.y + nv.z * nv.z + nv.w * nv.w;
        if (is_last) {
            float4 xv = x4[f];
            q4[tk * 32 + d4] = make_float4(xv.x - nv.x, xv.y - nv.y,
                                           xv.z - nv.z, xv.w - nv.w);
        }
    }
    #pragma unroll
    for (int o = 16; o > 0; o >>= 1) psum += __shfl_down_sync(0xffffffffu, psum, o);
    __syncthreads();
    if (lid == 0) psums[wid] = psum;
    __syncthreads();
    if (tid == 0) {
        float s = 0.f;
        #pragma unroll
        for (int w2 = 0; w2 < 8; w2++) s += psums[w2];
        g_partial[stage * NBLOCKS + blockIdx.x] = s;
    }
}

// ---------------------------------------------------------------------------
__global__ void finish_kernel(float* __restrict__ out) {
    int q = threadIdx.x;
    if (q < QSTAGES) {
        float s = 0.f;
        for (int b = 0; b < NBLOCKS; b++) s += g_partial[q * NBLOCKS + b];
        out[(size_t)TOKENS * QSTAGES + (size_t)TOKENS * DDIM + q] =
            s / (float)(TOKENS * DDIM);
    }
}

extern "C" void kernel_launch(void* const* d_in, const int* in_sizes, int n_in,
                              void* d_out, int out_size) {
    const float* x  = (const float*)d_in[0];
    const float* cb = (const float*)d_in[1];
    float* out = (float*)d_out;

    cudaFuncSetAttribute(stage_kernel,
                         cudaFuncAttributeMaxDynamicSharedMemorySize, SMEM_TOTAL);

    prep_kernel<<<64, 128>>>(cb);
    c2_kernel<<<1024, 256>>>(cb);
    for (int s = 0; s < QSTAGES; s++) {
        stage_kernel<<<NBLOCKS, NTHREADS, SMEM_TOTAL>>>(x, cb, out, s,
                                                        (s == QSTAGES - 1) ? 1 : 0);
    }
    finish_kernel<<<1, 32>>>(out);
}